// round 16
// baseline (speedup 1.0000x reference)
#include <cuda_runtime.h>

// TonalDiffusionModel — warp-per-row, register-resident stencil with dynamic
// active-window narrowing and Poisson weight folded into the stencil taps.
//
// Per row d (512): run[513] updated max_iter times by a 6-tap shift stencil
// (steps {1,-1,-3,3,4,-4}; mass leaving [0,512] dropped), accumulated with
// Poisson weights, then row-normalized.
//
// Key identity: with scaled state rt(n) = (lam^n/n!) * run(n),
//   acc  = sum_n rt(n)                          (plain adds, no scalar chain)
//   rt(n+1) = stencil_{p * lam/(n+1)}(rt(n))    (FRESH per-iter tap scale —
//             the previous factors are already carried by the state itself)
// exp(-lam) cancels in the normalization.
//
// Fast path: mass starting in [mn,mx] reaches at most [mn-4(I-1), mx+4(I-1)].
// If that window fits in 288 = 32*9 slots, lane l owns 9 contiguous window
// elements; zero halos at window edges are exact. Fallback: EPL=17 masked
// full-support path.
//
// Inputs: d_in[0] logw [512,6] f32; d_in[1] transition matrix (one-hot
// shifts, NOT read); d_in[2] init_dist [512,513] f32; d_in[3] max_iter i32.
// Output: f32 [512,513].

#define N_DATA   512
#define SUPPORT  513
#define N_STEPS  6
#define WPB      4
#define NT       (WPB * 32)
#define EPL_FAST 9
#define WIN_FAST (EPL_FAST * 32)   // 288

__constant__ float INV_N1[64] = {
    1.0f/1,  1.0f/2,  1.0f/3,  1.0f/4,  1.0f/5,  1.0f/6,  1.0f/7,  1.0f/8,
    1.0f/9,  1.0f/10, 1.0f/11, 1.0f/12, 1.0f/13, 1.0f/14, 1.0f/15, 1.0f/16,
    1.0f/17, 1.0f/18, 1.0f/19, 1.0f/20, 1.0f/21, 1.0f/22, 1.0f/23, 1.0f/24,
    1.0f/25, 1.0f/26, 1.0f/27, 1.0f/28, 1.0f/29, 1.0f/30, 1.0f/31, 1.0f/32,
    1.0f/33, 1.0f/34, 1.0f/35, 1.0f/36, 1.0f/37, 1.0f/38, 1.0f/39, 1.0f/40,
    1.0f/41, 1.0f/42, 1.0f/43, 1.0f/44, 1.0f/45, 1.0f/46, 1.0f/47, 1.0f/48,
    1.0f/49, 1.0f/50, 1.0f/51, 1.0f/52, 1.0f/53, 1.0f/54, 1.0f/55, 1.0f/56,
    1.0f/57, 1.0f/58, 1.0f/59, 1.0f/60, 1.0f/61, 1.0f/62, 1.0f/63, 1.0f/64
};

template<int EPL, bool MASK>
__device__ __forceinline__
void diffuse_row(const int lane, const int lo, const int max_iter,
                 const float* __restrict__ initrow,
                 float* __restrict__ outrow,
                 const float p0, const float p1, const float p2,
                 const float p3, const float p4, const float p5,
                 const float lam)
{
    const int base = lane * EPL;

    float r[EPL], acc[EPL], msk[EPL];
#pragma unroll
    for (int j = 0; j < EPL; j++) {
        const int t = lo + base + j;
        const bool in = (t < SUPPORT);
        msk[j] = in ? 1.0f : 0.0f;
        r[j]   = in ? initrow[t] : 0.0f;
        acc[j] = 0.0f;
    }

    // prologue halo exchange
    float lh[4], rh[4];
#pragma unroll
    for (int k = 0; k < 4; k++) {
        float a = __shfl_up_sync(0xFFFFFFFFu, r[EPL - 4 + k], 1);
        lh[k] = (lane == 0) ? 0.0f : a;
        float b = __shfl_down_sync(0xFFFFFFFFu, r[k], 1);
        rh[k] = (lane == 31) ? 0.0f : b;
    }

#pragma unroll 4
    for (int n = 0; n < max_iter; n++) {
        // accumulate current (pre-scaled) state — no scalar dependency
#pragma unroll
        for (int j = 0; j < EPL; j++) acc[j] += r[j];

        // FRESH per-iteration tap scaling: q = p * lam/(n+1).
        // (Previous factors live in the state; do NOT compound q.)
        const float cinv = (n < 64) ? INV_N1[n] : __fdividef(1.0f, (float)(n + 1));
        const float s = lam * cinv;
        const float q0 = p0 * s, q1 = p1 * s, q2 = p2 * s;
        const float q3 = p3 * s, q4 = p4 * s, q5 = p5 * s;

        // extended view e[0..EPL+7] = [lh(4) | r(EPL) | rh(4)]
        float e[EPL + 8];
#pragma unroll
        for (int k = 0; k < 4; k++) { e[k] = lh[k]; e[EPL + 4 + k] = rh[k]; }
#pragma unroll
        for (int j = 0; j < EPL; j++) e[4 + j] = r[j];

        // run'[t] = q0*e[t-1]+q1*e[t+1]+q2*e[t+3]+q3*e[t-3]+q4*e[t-4]+q5*e[t+4]
#define STEN(j) fmaf(q5, e[4+(j)+4], fmaf(q4, e[4+(j)-4], fmaf(q3, e[4+(j)-3], \
                fmaf(q2, e[4+(j)+3], fmaf(q1, e[4+(j)+1], q0 * e[4+(j)-1])))))

        // 1) boundary outputs first ...
        float nbL[4], nbR[4];
#pragma unroll
        for (int k = 0; k < 4; k++) {
            nbL[k] = STEN(k);
            if (MASK) nbL[k] *= msk[k];
        }
#pragma unroll
        for (int k = 0; k < 4; k++) {
            nbR[k] = STEN(EPL - 4 + k);
            if (MASK) nbR[k] *= msk[EPL - 4 + k];
        }
        // 2) ... so next-iter halo shuffles issue early (hidden by 3)
#pragma unroll
        for (int k = 0; k < 4; k++) {
            float a = __shfl_up_sync(0xFFFFFFFFu, nbR[k], 1);
            float b = __shfl_down_sync(0xFFFFFFFFu, nbL[k], 1);
            lh[k] = (lane == 0) ? 0.0f : a;
            rh[k] = (lane == 31) ? 0.0f : b;
        }
        // 3) interior (halo-independent)
        float ni[(EPL - 8) > 0 ? (EPL - 8) : 1];
#pragma unroll
        for (int j = 4; j < EPL - 4; j++) {
            ni[j - 4] = STEN(j);
            if (MASK) ni[j - 4] *= msk[j];
        }
#undef STEN
        // commit
#pragma unroll
        for (int k = 0; k < 4; k++) { r[k] = nbL[k]; r[EPL - 4 + k] = nbR[k]; }
#pragma unroll
        for (int j = 4; j < EPL - 4; j++) r[j] = ni[j - 4];
    }

    // normalization: warp-wide sum of acc
    float local = 0.0f;
#pragma unroll
    for (int j = 0; j < EPL; j++) local += acc[j];
#pragma unroll
    for (int off = 16; off > 0; off >>= 1)
        local += __shfl_xor_sync(0xFFFFFFFFu, local, off);
    const float inv_total = 1.0f / local;

#pragma unroll
    for (int j = 0; j < EPL; j++) {
        const int t = lo + base + j;
        if (t < SUPPORT) outrow[t] = acc[j] * inv_total;
    }
}

__global__ __launch_bounds__(NT)
void tonal_diffusion_kernel(const float* __restrict__ logw,
                            const float* __restrict__ init_dist,
                            const int*   __restrict__ maxit_ptr,
                            float*       __restrict__ out)
{
    const int lane = threadIdx.x & 31;
    const int d    = blockIdx.x * WPB + (threadIdx.x >> 5);
    const int max_iter = *maxit_ptr;

    // per-row step probabilities
    float w[N_STEPS];
    float lam = 0.0f;
#pragma unroll
    for (int i = 0; i < N_STEPS; i++) {
        w[i] = __expf(logw[d * N_STEPS + i]);
        lam += w[i];
    }
    const float inv_lam = 1.0f / lam;
#pragma unroll
    for (int i = 0; i < N_STEPS; i++) w[i] *= inv_lam;

    const float* initrow = init_dist + d * SUPPORT;
    float*       outrow  = out + d * SUPPORT;

    // nonzero extent of this row's init
    int mn = SUPPORT, mx = -1;
#pragma unroll
    for (int k = 0; k < 17; k++) {
        const int t = lane + 32 * k;
        if (t < SUPPORT) {
            const float v = initrow[t];
            if (v != 0.0f) { mn = min(mn, t); mx = max(mx, t); }
        }
    }
#pragma unroll
    for (int off = 16; off > 0; off >>= 1) {
        mn = min(mn, __shfl_xor_sync(0xFFFFFFFFu, mn, off));
        mx = max(mx, __shfl_xor_sync(0xFFFFFFFFu, mx, off));
    }

    int reach = 4 * (max_iter - 1);
    if (reach < 0) reach = 0;
    const int lo_need = max(0, mn - reach);
    const int hi_need = min(SUPPORT - 1, mx + reach);
    const int width   = hi_need - lo_need + 1;

    if (mx >= 0 && width <= WIN_FAST) {
        int lo = min(lo_need, SUPPORT - WIN_FAST);   // 225 >= 0
        // zero everything outside the compute window
        for (int t = lane; t < SUPPORT; t += 32)
            if (t < lo || t >= lo + WIN_FAST) outrow[t] = 0.0f;
        diffuse_row<EPL_FAST, false>(lane, lo, max_iter, initrow, outrow,
                                     w[0], w[1], w[2], w[3], w[4], w[5], lam);
    } else {
        diffuse_row<17, true>(lane, 0, max_iter, initrow, outrow,
                              w[0], w[1], w[2], w[3], w[4], w[5], lam);
    }
}

extern "C" void kernel_launch(void* const* d_in, const int* in_sizes, int n_in,
                              void* d_out, int out_size)
{
    const float* logw      = (const float*)d_in[0];
    // d_in[1] = transition_matrix: structurally known one-hot shifts; not read.
    const float* init_dist = (const float*)d_in[2];
    const int*   maxit     = (const int*)d_in[3];
    float*       out       = (float*)d_out;

    tonal_diffusion_kernel<<<N_DATA / WPB, NT>>>(logw, init_dist, maxit, out);
}